// round 12
// baseline (speedup 1.0000x reference)
#include <cuda_runtime.h>

// B=64, T=512, E=8192
// out[b][j] = (1/count) * sum_{r=r0}^{511} x[b*T*E + (j+512) + r*8191]
//   r0 = max(0, j - 7679), count = 512 - r0, j in [0, 8190].
//
// Single fused kernel: 4 r-quarter CTAs per (b, j-tile) write partials to
// scratch; the LAST CTA of each group (arrival counter) combines the 4
// partials (L2-hot) and writes the output. No second launch.

#define B_DIM 64
#define T_DIM 512
#define E_DIM 8192
#define OUT_COLS (E_DIM - 1)          // 8191
#define ROW_STRIDE (E_DIM - 1)        // 8191
#define J_FULL (E_DIM - T_DIM - 1)    // 7679
#define BLOCK 256
#define JTILES (E_DIM / BLOCK)        // 32
#define FULL_TILES 30                 // tiles 0..29: j <= 7679 (full count)
#define NQ 4
#define R_Q (T_DIM / NQ)              // 128 rows per quarter
#define R_H (R_Q / 2)                 // 64 rows per stream
#define H_OFF ((unsigned)(R_H * ROW_STRIDE))

// Partial sums [q][b][j] (8 MB) + arrival counters (zero-init at load,
// reset to 0 by the last CTA each run -> deterministic across replays).
__device__ float g_part[NQ * B_DIM * E_DIM];
__device__ unsigned g_count[B_DIM * JTILES];

__global__ __launch_bounds__(BLOCK, 8) void antidiag_fused_kernel(
    const float* __restrict__ x, float* __restrict__ out)
{
    const int tid = threadIdx.x;
    const int jt  = blockIdx.x;
    const int b   = blockIdx.y;
    const int q   = blockIdx.z;
    const int j   = jt * BLOCK + tid;
    const bool valid = (j < OUT_COLS);

    // ---- phase 1: partial sum over this CTA's r-quarter ----
    float s = 0.0f;
    if (valid) {
        const float* __restrict__ p =
            x + (size_t)b * T_DIM * E_DIM + (size_t)(j + T_DIM);
        const int rbeg = q * R_Q;
        if (jt < FULL_TILES) {
            // hot path: two 64-row streams, unroll 8 -> 16-LDG window
            const float* ph = p + (size_t)rbeg * ROW_STRIDE;
            float s0 = 0.f, s1 = 0.f;
            #pragma unroll 8
            for (int r = 0; r < R_H; ++r) {
                const unsigned off = (unsigned)(r * ROW_STRIDE);
                s0 += ph[off];
                s1 += ph[off + H_OFF];
            }
            s = s0 + s1;
        } else {
            // ragged tail (j in [7680, 8190]): clamp quarter start to r0
            const int r0 = j - J_FULL;           // >= 1 here
            const int rs = (r0 > rbeg) ? r0 : rbeg;
            const int re = rbeg + R_Q;
            #pragma unroll 8
            for (int r = rs; r < re; ++r)
                s += p[(unsigned)(r * ROW_STRIDE)];
        }
        g_part[((size_t)q * B_DIM + b) * E_DIM + j] = s;
    }

    // ---- arrival: is this the last of the NQ CTAs in this (b, jt) group? ----
    __shared__ unsigned s_last;
    __threadfence();                   // make partial visible gpu-wide
    __syncthreads();                   // all threads' stores precede the count
    if (tid == 0) {
        const unsigned old = atomicAdd(&g_count[b * JTILES + jt], 1u);
        s_last = (old == NQ - 1) ? 1u : 0u;
    }
    __syncthreads();
    if (!s_last) return;

    // ---- phase 2 (last CTA only): combine 4 partials, write output ----
    if (valid) {
        float acc = 0.0f;
        #pragma unroll
        for (int qq = 0; qq < NQ; ++qq)
            acc += g_part[((size_t)qq * B_DIM + b) * E_DIM + j];
        const int r0 = (j > J_FULL) ? (j - J_FULL) : 0;
        out[(size_t)b * OUT_COLS + j] = acc * (1.0f / (float)(T_DIM - r0));
    }
    if (tid == 0)
        g_count[b * JTILES + jt] = 0u;   // reset for next graph replay
}

extern "C" void kernel_launch(void* const* d_in, const int* in_sizes, int n_in,
                              void* d_out, int out_size)
{
    const float* x = (const float*)d_in[0];
    float* out = (float*)d_out;

    dim3 block(BLOCK);
    dim3 grid(JTILES, B_DIM, NQ);   // 32 x 64 x 4 = 8192 CTAs
    antidiag_fused_kernel<<<grid, block>>>(x, out);
}

// round 13
// speedup vs baseline: 1.0025x; 1.0025x over previous
#include <cuda_runtime.h>

// B=64, T=512, E=8192
// out[b][j] = (1/count) * sum_{r=r0}^{511} x[b*T*E + (j+512) + r*8191]
//   r0 = max(0, j - 7679), count = 512 - r0, j in [0, 8190].
//
// Atomic-epilogue scheme: a tiny kernel zeroes out, then 4 r-quarter CTAs
// per (b, j-tile) each atomicAdd their PRE-SCALED partial (s / count) into
// out. No scratch round-trip, no fence, no combine launch.

#define B_DIM 64
#define T_DIM 512
#define E_DIM 8192
#define OUT_COLS (E_DIM - 1)          // 8191
#define ROW_STRIDE (E_DIM - 1)        // 8191
#define J_FULL (E_DIM - T_DIM - 1)    // 7679
#define BLOCK 256
#define JTILES (E_DIM / BLOCK)        // 32
#define FULL_TILES 30                 // tiles 0..29: j <= 7679 (full count)
#define NQ 4
#define R_Q (T_DIM / NQ)              // 128 rows per quarter
#define R_H (R_Q / 2)                 // 64 rows per stream
#define H_OFF ((unsigned)(R_H * ROW_STRIDE))

#define OUT_TOTAL (B_DIM * OUT_COLS)  // 524224 floats

__global__ __launch_bounds__(256) void zero_out_kernel(float* __restrict__ out)
{
    // 524224 floats = 131056 float4. 512 CTAs x 256 threads x 1 float4 each.
    const int i = blockIdx.x * 256 + threadIdx.x;
    if (4 * i + 3 < OUT_TOTAL) {
        reinterpret_cast<float4*>(out)[i] =
            make_float4(0.f, 0.f, 0.f, 0.f);
    } else {
        for (int k = 4 * i; k < OUT_TOTAL; ++k) out[k] = 0.f;
    }
}

__global__ __launch_bounds__(BLOCK, 8) void antidiag_atomic_kernel(
    const float* __restrict__ x, float* __restrict__ out)
{
    const int tid = threadIdx.x;
    const int jt  = blockIdx.x;
    const int b   = blockIdx.y;
    const int q   = blockIdx.z;
    const int j   = jt * BLOCK + tid;
    if (j >= OUT_COLS) return;

    const float* __restrict__ p =
        x + (size_t)b * T_DIM * E_DIM + (size_t)(j + T_DIM);
    const int rbeg = q * R_Q;

    float s = 0.0f;
    int count;
    if (jt < FULL_TILES) {
        // hot path: full quarter, two 64-row streams, unroll 8 -> 16-LDG window
        const float* ph = p + (size_t)rbeg * ROW_STRIDE;
        float s0 = 0.f, s1 = 0.f;
        #pragma unroll 8
        for (int r = 0; r < R_H; ++r) {
            const unsigned off = (unsigned)(r * ROW_STRIDE);
            s0 += ph[off];
            s1 += ph[off + H_OFF];
        }
        s = s0 + s1;
        count = T_DIM;
    } else {
        // ragged tail (j in [7680, 8190]): clamp quarter start to r0
        const int r0 = j - J_FULL;               // >= 1 here
        const int rs = (r0 > rbeg) ? r0 : rbeg;
        const int re = rbeg + R_Q;
        #pragma unroll 8
        for (int r = rs; r < re; ++r)
            s += p[(unsigned)(r * ROW_STRIDE)];
        count = T_DIM - r0;
    }

    // Pre-scaled atomic accumulate: sum over quarters of s/count = mean.
    atomicAdd(&out[(size_t)b * OUT_COLS + j], s * (1.0f / (float)count));
}

extern "C" void kernel_launch(void* const* d_in, const int* in_sizes, int n_in,
                              void* d_out, int out_size)
{
    const float* x = (const float*)d_in[0];
    float* out = (float*)d_out;

    // 1) zero the (0xAA-poisoned) output
    zero_out_kernel<<<(OUT_TOTAL / 4 + 255) / 256, 256>>>(out);

    // 2) partial sums with pre-scaled atomic accumulation
    dim3 block(BLOCK);
    dim3 grid(JTILES, B_DIM, NQ);   // 32 x 64 x 4 = 8192 CTAs
    antidiag_atomic_kernel<<<grid, block>>>(x, out);
}

// round 14
// speedup vs baseline: 1.0485x; 1.0459x over previous
#include <cuda_runtime.h>

// B=64, T=512, E=8192
// out[b][j] = (1/count) * sum_{r=r0}^{511} x[b*T*E + (j+512) + r*8191]
//   r0 = max(0, j - 7679), count = 512 - r0, j in [0, 8190].
//
// Single kernel, intra-CTA r-split: 1024-thread CTA = 256 j-columns x 4
// r-quarters. Each thread sums its quarter (two 64-row streams); quarters
// 1..3 stash partials in smem; q=0 combines and writes the mean. The wave
// geometry (2048 CTAs @ 2/SM = 6.9 uniform waves) matches the fastest
// measured phase-1, with zero scratch traffic and zero epilogue launches.

#define B_DIM 64
#define T_DIM 512
#define E_DIM 8192
#define OUT_COLS (E_DIM - 1)          // 8191
#define ROW_STRIDE (E_DIM - 1)        // 8191
#define J_FULL (E_DIM - T_DIM - 1)    // 7679
#define JCOLS 256                     // j per CTA
#define NQ 4                          // r-quarters per CTA
#define BLOCK (JCOLS * NQ)            // 1024 threads
#define JTILES (E_DIM / JCOLS)        // 32
#define FULL_TILES 30                 // tiles 0..29: j <= 7679 (full count)
#define R_Q (T_DIM / NQ)              // 128 rows per quarter
#define R_H (R_Q / 2)                 // 64 rows per stream
#define H_OFF ((unsigned)(R_H * ROW_STRIDE))

__global__ __launch_bounds__(BLOCK, 2) void antidiag_mean_kernel(
    const float* __restrict__ x, float* __restrict__ out)
{
    __shared__ float s_part[(NQ - 1) * JCOLS];   // 3 KB

    const int tid  = threadIdx.x;
    const int jcol = tid & (JCOLS - 1);
    const int q    = tid >> 8;                   // 0..3
    const int jt   = blockIdx.x;
    const int b    = blockIdx.y;
    const int j    = jt * JCOLS + jcol;
    const bool valid = (j < OUT_COLS);

    float s = 0.0f;
    if (valid) {
        const float* __restrict__ p =
            x + (size_t)b * T_DIM * E_DIM + (size_t)(j + T_DIM);
        const int rbeg = q * R_Q;
        if (jt < FULL_TILES) {
            // hot path: full quarter, two 64-row streams, unroll 8
            // -> 16 independent LDGs per scoreboard window (proven shape).
            const float* ph = p + (size_t)rbeg * ROW_STRIDE;
            float s0 = 0.f, s1 = 0.f;
            #pragma unroll 8
            for (int r = 0; r < R_H; ++r) {
                const unsigned off = (unsigned)(r * ROW_STRIDE);
                s0 += ph[off];
                s1 += ph[off + H_OFF];
            }
            s = s0 + s1;
        } else {
            // ragged tail (j in [7680, 8190]): clamp quarter start to r0
            const int r0 = j - J_FULL;           // >= 1 here
            const int rs = (r0 > rbeg) ? r0 : rbeg;
            const int re = rbeg + R_Q;
            #pragma unroll 8
            for (int r = rs; r < re; ++r)
                s += p[(unsigned)(r * ROW_STRIDE)];
        }
    }

    // quarters 1..3 publish partials; quarter 0 combines and writes.
    if (q > 0)
        s_part[(q - 1) * JCOLS + jcol] = s;
    __syncthreads();

    if (q == 0 && valid) {
        // consecutive jcol -> consecutive banks: conflict-free LDS.
        float acc = s + s_part[jcol]
                      + s_part[JCOLS + jcol]
                      + s_part[2 * JCOLS + jcol];
        const int r0 = (j > J_FULL) ? (j - J_FULL) : 0;
        out[(size_t)b * OUT_COLS + j] = acc * (1.0f / (float)(T_DIM - r0));
    }
}

extern "C" void kernel_launch(void* const* d_in, const int* in_sizes, int n_in,
                              void* d_out, int out_size)
{
    const float* x = (const float*)d_in[0];
    float* out = (float*)d_out;

    dim3 block(BLOCK);
    dim3 grid(JTILES, B_DIM);        // 32 x 64 = 2048 CTAs of 1024 threads
    antidiag_mean_kernel<<<grid, block>>>(x, out);
}